// round 15
// baseline (speedup 1.0000x reference)
#include <cuda_runtime.h>
#include <cuda_bf16.h>
#include <cstdint>

// ── Constants — 2 independent batch groups x 64 CTAs = 128 SMs ──────────────
#define NGRP      2
#define GCTAS     64
#define NCTA      (NGRP * GCTAS)
#define NTHREADS  256                 // 8 warps
#define BB        16
#define GB        8                   // batches per group == MMA N
#define TT        1024
#define DD        768
#define DPC       12                  // d-columns per CTA (64*12 = 768)
#define NROWS     48                  // gate rows = DPC*4 (r = cd*4 + gate)
#define NW        8                   // warps; each owns 96-k slice
#define KW        96                  // k per warp
#define KST       6                   // m16n8k16 K-steps per warp (6*16 = 96)
#define NMT       3                   // M-tiles of 16 (3*16 = 48)
#define REDW      416                 // floats per warp spill row: 8 n x 52
#define NPITCH    52                  // padded floats per n (48 rows, 16B-aligned, conflict-free)

// ── Globals (no allocation anywhere) ────────────────────────────────────────
__device__ __align__(16) __nv_bfloat16 g_hhi[2][BB * DD];
__device__ __align__(16) __nv_bfloat16 g_hlo[2][BB * DD];
__device__ unsigned g_ctr[NGRP * 32];

// ── Helpers ─────────────────────────────────────────────────────────────────
static __device__ __forceinline__ uint32_t pack_bf2(__nv_bfloat16 a, __nv_bfloat16 b) {
    union { __nv_bfloat16 u[2]; uint32_t q; } p;
    p.u[0] = a; p.u[1] = b;           // lower half = lower-k element
    return p.q;
}
static __device__ __forceinline__ uint32_t ldcv_u32(const void* p) {
    uint32_t v;
    asm volatile("ld.global.cv.u32 %0, [%1];" : "=r"(v) : "l"(p));
    return v;
}
// m16n8k16 row.col bf16 MMA, f32 accum (sm_80+ path; compiles on plain sm_103)
#define MMA16816(c, a, b0, b1)                                                  \
    asm volatile(                                                               \
        "mma.sync.aligned.m16n8k16.row.col.f32.bf16.bf16.f32 "                  \
        "{%0,%1,%2,%3}, {%4,%5,%6,%7}, {%8,%9}, {%0,%1,%2,%3};"                 \
        : "+f"((c)[0]), "+f"((c)[1]), "+f"((c)[2]), "+f"((c)[3])                \
        : "r"((a)[0]), "r"((a)[1]), "r"((a)[2]), "r"((a)[3]), "r"(b0), "r"(b1))

// Zero the barrier counters before each run (graph replays reuse device globals).
__global__ void rnn_reset_kernel() {
    if (threadIdx.x < NGRP * 32) g_ctr[threadIdx.x] = 0u;
}

__global__ void __launch_bounds__(NTHREADS, 1)
rnn_mma_kernel(const float* __restrict__ states,
               const float* __restrict__ Wx,
               const float* __restrict__ R,
               const float* __restrict__ bias,
               float* __restrict__ out)
{
    // Dynamic smem: only the spill/reduce scratch. 8 warps x 416 floats = 13KB.
    extern __shared__ float red[];

    const int tid = threadIdx.x;
    const int grp = blockIdx.x >> 6;     // batch group 0/1
    const int cta = blockIdx.x & 63;     // CTA within group
    const int w   = tid >> 5;            // warp id (0..7) -> 96-k slice
    const int l   = tid & 31;
    const int gid = l >> 2;              // MMA group id (row / n selector)
    const int tig = l & 3;               // thread-in-group (k / col selector)
    const int d0  = cta * DPC;
    const int kb  = w * KW;              // warp's k base

    // ── One-time: R slice -> register-resident MMA A fragments (bf16 hi/lo).
    // A[r][k] = R[g= r&3][k][d0 + (r>>2)]. Fragment (m,s): rows m*16+gid(+8),
    // cols kb+s*16 + {tig*2, tig*2+1, tig*2+8, tig*2+9}.
    uint32_t Ahi[NMT][KST][4], Alo[NMT][KST][4];    // 144 registers
    {
        #pragma unroll
        for (int m = 0; m < NMT; ++m) {
            #pragma unroll
            for (int s = 0; s < KST; ++s) {
                #pragma unroll
                for (int q = 0; q < 4; ++q) {
                    const int r = m * 16 + gid + ((q & 1) ? 8 : 0);
                    const int k = kb + s * 16 + tig * 2 + ((q >> 1) ? 8 : 0);
                    const int g = r & 3, cdl = r >> 2;
                    const float v0 = R[((size_t)g * DD + k)     * DD + d0 + cdl];
                    const float v1 = R[((size_t)g * DD + k + 1) * DD + d0 + cdl];
                    const __nv_bfloat16 h0 = __float2bfloat16(v0);
                    const __nv_bfloat16 h1 = __float2bfloat16(v1);
                    const __nv_bfloat16 l0 = __float2bfloat16(v0 - __bfloat162float(h0));
                    const __nv_bfloat16 l1 = __float2bfloat16(v1 - __bfloat162float(h1));
                    Ahi[m][s][q] = pack_bf2(h0, h1);
                    Alo[m][s][q] = pack_bf2(l0, l1);
                }
            }
        }
    }

    // ── One-time: per-cell state + t=0 output rows. 96 cell threads. ──
    float c_state = 0.f;
    int gb = 0, cbl = 0, cd = 0;
    if (tid < GB * DPC) {
        cbl = tid / DPC;
        cd  = tid - cbl * DPC;
        gb  = grp * GB + cbl;
        const int d = d0 + cd;
        const float h0 = states[(size_t)(0 * BB + gb) * DD + d];
        c_state        = states[(size_t)(1 * BB + gb) * DD + d];
        out[((size_t)(0 * BB + gb) * (TT + 1) + 0) * DD + d] = h0;
        out[((size_t)(1 * BB + gb) * (TT + 1) + 0) * DD + d] = c_state;
    }

    volatile unsigned* ctr = &g_ctr[grp * 32];

    // ── Main recurrence ──
    for (int t = 0; t < TT; ++t) {
        // Phase 1: Wx(t) + bias loads (cell threads; consumed after S3).
        float wxi = 0.f, wxf = 0.f, wxz = 0.f, wxo = 0.f;
        if (tid < GB * DPC) {
            const int d = d0 + cd;
            const float* wp = Wx + ((size_t)gb * TT + t) * (4 * DD) + d;
            wxi = wp[0 * DD] + bias[0 * DD + d];
            wxf = wp[1 * DD] + bias[1 * DD + d];
            wxz = wp[2 * DD] + bias[2 * DD + d];
            wxo = wp[3 * DD] + bias[3 * DD + d];
        }

        // Phase 2+3: GEMM. B fragments loaded per-lane straight from global
        // (.cv -> always L2-fresh; no staging, no fence). 9 MMAs per K-step:
        // 3 M-tiles x (Ahi*Bhi + Ahi*Blo + Alo*Bhi).  54 HMMA / warp / step.
        float acc[NMT][4];
        #pragma unroll
        for (int m = 0; m < NMT; ++m)
            #pragma unroll
            for (int q = 0; q < 4; ++q) acc[m][q] = 0.f;

        if (t == 0) {
            // h(0) from fp32 states: convert per lane.
            const float* sp = states + (size_t)(grp * GB + gid) * DD;
            #pragma unroll
            for (int s = 0; s < KST; ++s) {
                const int ko = kb + s * 16 + tig * 2;
                const float v0 = sp[ko],     v1 = sp[ko + 1];
                const float v2 = sp[ko + 8], v3 = sp[ko + 9];
                const __nv_bfloat16 h0 = __float2bfloat16(v0), h1 = __float2bfloat16(v1);
                const __nv_bfloat16 h2 = __float2bfloat16(v2), h3 = __float2bfloat16(v3);
                const uint32_t bh0 = pack_bf2(h0, h1);
                const uint32_t bh1 = pack_bf2(h2, h3);
                const uint32_t bl0 = pack_bf2(__float2bfloat16(v0 - __bfloat162float(h0)),
                                              __float2bfloat16(v1 - __bfloat162float(h1)));
                const uint32_t bl1 = pack_bf2(__float2bfloat16(v2 - __bfloat162float(h2)),
                                              __float2bfloat16(v3 - __bfloat162float(h3)));
                #pragma unroll
                for (int m = 0; m < NMT; ++m) MMA16816(acc[m], Ahi[m][s], bh0, bh1);
                #pragma unroll
                for (int m = 0; m < NMT; ++m) MMA16816(acc[m], Ahi[m][s], bl0, bl1);
                #pragma unroll
                for (int m = 0; m < NMT; ++m) MMA16816(acc[m], Alo[m][s], bh0, bh1);
            }
        } else {
            const __nv_bfloat16* sh = g_hhi[t & 1] + ((size_t)grp * GB + gid) * DD;
            const __nv_bfloat16* sl = g_hlo[t & 1] + ((size_t)grp * GB + gid) * DD;
            #pragma unroll
            for (int s = 0; s < KST; ++s) {
                const int ko = kb + s * 16 + tig * 2;
                const uint32_t bh0 = ldcv_u32(sh + ko);
                const uint32_t bh1 = ldcv_u32(sh + ko + 8);
                const uint32_t bl0 = ldcv_u32(sl + ko);
                const uint32_t bl1 = ldcv_u32(sl + ko + 8);
                #pragma unroll
                for (int m = 0; m < NMT; ++m) MMA16816(acc[m], Ahi[m][s], bh0, bh1);
                #pragma unroll
                for (int m = 0; m < NMT; ++m) MMA16816(acc[m], Ahi[m][s], bl0, bl1);
                #pragma unroll
                for (int m = 0; m < NMT; ++m) MMA16816(acc[m], Alo[m][s], bh0, bh1);
            }
        }

        // Phase 4: spill C fragments. red[w][n*NPITCH + r]; banks conflict-free
        // ((tig*2*52 + gid) % 32 distinct over the warp).
        {
            float* rw = red + (size_t)w * REDW;
            #pragma unroll
            for (int m = 0; m < NMT; ++m) {
                const int r0 = m * 16 + gid;
                const int n0 = tig * 2;
                rw[(n0    ) * NPITCH + r0    ] = acc[m][0];
                rw[(n0 + 1) * NPITCH + r0    ] = acc[m][1];
                rw[(n0    ) * NPITCH + r0 + 8] = acc[m][2];
                rw[(n0 + 1) * NPITCH + r0 + 8] = acc[m][3];
            }
        }
        __syncthreads();   // S3: all spills visible

        // Phase 5: cell threads reduce over 8 warp slices (one float4 each:
        // rows cd*4..cd*4+3 = gates i,f,z,o) and run the LSTM update.
        float hn = 0.f, cn = 0.f;
        if (tid < GB * DPC) {
            const int off = cbl * NPITCH + cd * 4;
            float4 g4 = make_float4(0.f, 0.f, 0.f, 0.f);
            #pragma unroll
            for (int ww = 0; ww < NW; ++ww) {
                const float4 p = *(const float4*)(red + (size_t)ww * REDW + off);
                g4.x += p.x; g4.y += p.y; g4.z += p.z; g4.w += p.w;
            }
            const float gi = g4.x + wxi;
            const float gf = g4.y + wxf;
            const float gz = g4.z + wxz;
            const float go = g4.w + wxo;
            const float i_ = 1.f / (1.f + __expf(-gi));
            const float f_ = 1.f / (1.f + __expf(-gf));
            const float z_ = tanhf(gz);
            const float o_ = 1.f / (1.f + __expf(-go));
            cn = f_ * c_state + i_ * z_;
            hn = o_ * tanhf(cn);
            c_state = cn;
            // Exchange as bf16 hi/lo (consumers load fragments directly).
            const __nv_bfloat16 hh = __float2bfloat16(hn);
            const __nv_bfloat16 hl = __float2bfloat16(hn - __bfloat162float(hh));
            const size_t idx = (size_t)gb * DD + d0 + cd;
            g_hhi[(t + 1) & 1][idx] = hh;
            g_hlo[(t + 1) & 1][idx] = hl;
        }

        // Phase 6: PER-GROUP grid barrier (proven R12/R13 shape: one fence +
        // one atomicAdd per CTA; per-warp lane-0 volatile poll release).
        __syncthreads();                   // S_flag: all h stores issued
        if (tid == 0) {
            __threadfence();
            atomicAdd((unsigned*)ctr, 1u);
        }
        // Off-critical-path: fp32 out rows for t+1 (never read cross-CTA).
        if (tid < GB * DPC) {
            const int d = d0 + cd;
            out[((size_t)(0 * BB + gb) * (TT + 1) + (t + 1)) * DD + d] = hn;
            out[((size_t)(1 * BB + gb) * (TT + 1) + (t + 1)) * DD + d] = cn;
        }
        {
            const unsigned target = (unsigned)(GCTAS) * (unsigned)(t + 1);
            if (l == 0) {
                while (*ctr < target) { }
            }
            __syncwarp();
        }
    }
}

extern "C" void kernel_launch(void* const* d_in, const int* in_sizes, int n_in,
                              void* d_out, int out_size)
{
    const float* states = (const float*)d_in[0];  // [2,16,1,768]
    const float* Wx     = (const float*)d_in[1];  // [16,1024,4,1,768]
    const float* R      = (const float*)d_in[2];  // [4,1,768,768]
    const float* bias   = (const float*)d_in[3];  // [4,1,768]
    float*       out    = (float*)d_out;          // [2,16,1025,1,768]

    const size_t smem_bytes = (size_t)NW * REDW * sizeof(float);  // 13312 B

    rnn_reset_kernel<<<1, 64>>>();
    rnn_mma_kernel<<<NCTA, NTHREADS, smem_bytes>>>(states, Wx, R, bias, out);
}

// round 17
// speedup vs baseline: 1.3820x; 1.3820x over previous
#include <cuda_runtime.h>
#include <cuda_bf16.h>
#include <cstdint>

// ── Constants — 2 independent batch groups x 64 CTAs = 128 SMs ──────────────
#define NGRP      2
#define GCTAS     64
#define NCTA      (NGRP * GCTAS)
#define NTHREADS  256                 // 8 warps
#define BB        16
#define GB        8                   // batches per group == MMA N
#define TT        1024
#define DD        768
#define DPC       12                  // d-columns per CTA (64*12 = 768)
#define NROWS     48                  // gate rows = DPC*4 (r = cd*4 + gate)
#define NW        8                   // warps; each owns 96-k slice
#define KW        96                  // k per warp
#define KST       6                   // m16n8k16 K-steps per warp (6*16 = 96)
#define NMT       3                   // M-tiles of 16 (3*16 = 48)
#define REDW      416                 // floats per warp spill row: 8 n x 52
#define NPITCH    52                  // padded floats per n (conflict-free)
#define HPITCH    776                 // u32 per smem h row (768 + 8 pad)

// ── Globals (no allocation anywhere) ────────────────────────────────────────
// h exchanged as ONE packed u32 per element: low 16 = bf16 hi, high 16 = bf16 lo.
__device__ __align__(16) unsigned g_h[2][BB * DD];
__device__ unsigned g_ctr[NGRP * 32];   // 128B-padded per-group counters

// ── Helpers ─────────────────────────────────────────────────────────────────
static __device__ __forceinline__ unsigned pack_hilo(float v) {
    const __nv_bfloat16 h = __float2bfloat16(v);
    const __nv_bfloat16 l = __float2bfloat16(v - __bfloat162float(h));
    union { __nv_bfloat16 u[2]; unsigned q; } p;
    p.u[0] = h; p.u[1] = l;
    return p.q;
}
static __device__ __forceinline__ void ldcv_u4(uint4& v, const void* p) {
    asm volatile("ld.global.cv.v4.u32 {%0,%1,%2,%3}, [%4];"
                 : "=r"(v.x), "=r"(v.y), "=r"(v.z), "=r"(v.w) : "l"(p));
}
// m16n8k16 row.col bf16 MMA, f32 accum (sm_80+ path; compiles on plain sm_103)
#define MMA16816(c, a, b0, b1)                                                  \
    asm volatile(                                                               \
        "mma.sync.aligned.m16n8k16.row.col.f32.bf16.bf16.f32 "                  \
        "{%0,%1,%2,%3}, {%4,%5,%6,%7}, {%8,%9}, {%0,%1,%2,%3};"                 \
        : "+f"((c)[0]), "+f"((c)[1]), "+f"((c)[2]), "+f"((c)[3])                \
        : "r"((a)[0]), "r"((a)[1]), "r"((a)[2]), "r"((a)[3]), "r"(b0), "r"(b1))

// Zero the barrier counters before each run (graph replays reuse device globals).
__global__ void rnn_reset_kernel() {
    if (threadIdx.x < NGRP * 32) g_ctr[threadIdx.x] = 0u;
}

__global__ void __launch_bounds__(NTHREADS, 1)
rnn_mma_kernel(const float* __restrict__ states,
               const float* __restrict__ Wx,
               const float* __restrict__ R,
               const float* __restrict__ bias,
               float* __restrict__ out)
{
    // Dynamic smem: staged h (8 x 776 u32 = 24832B) + spill scratch (13312B).
    extern __shared__ unsigned smem_u[];
    unsigned* sm_h = smem_u;                          // [GB][HPITCH] packed u32
    float*    red  = (float*)(smem_u + GB * HPITCH);  // [NW][REDW]

    const int tid = threadIdx.x;
    const int grp = blockIdx.x >> 6;     // batch group 0/1
    const int cta = blockIdx.x & 63;     // CTA within group
    const int w   = tid >> 5;            // warp id (0..7) -> 96-k slice
    const int l   = tid & 31;
    const int gid = l >> 2;              // MMA group id (row / n selector)
    const int tig = l & 3;               // thread-in-group (k / col selector)
    const int d0  = cta * DPC;
    const int kb  = w * KW;              // warp's k base

    // ── One-time: R slice -> register-resident MMA A fragments (bf16 hi/lo).
    uint32_t Ahi[NMT][KST][4], Alo[NMT][KST][4];    // 144 registers
    {
        #pragma unroll
        for (int m = 0; m < NMT; ++m) {
            #pragma unroll
            for (int s = 0; s < KST; ++s) {
                #pragma unroll
                for (int q = 0; q < 4; ++q) {
                    const int r = m * 16 + gid + ((q & 1) ? 8 : 0);
                    const int k = kb + s * 16 + tig * 2 + ((q >> 1) ? 8 : 0);
                    const int g = r & 3, cdl = r >> 2;
                    const unsigned p0 = pack_hilo(R[((size_t)g * DD + k)     * DD + d0 + cdl]);
                    const unsigned p1 = pack_hilo(R[((size_t)g * DD + k + 1) * DD + d0 + cdl]);
                    Ahi[m][s][q] = __byte_perm(p0, p1, 0x5410);
                    Alo[m][s][q] = __byte_perm(p0, p1, 0x7632);
                }
            }
        }
    }

    // ── One-time: per-cell state + t=0 output rows. 96 cell threads. ──
    float c_state = 0.f;
    int gb = 0, cbl = 0, cd = 0;
    if (tid < GB * DPC) {
        cbl = tid / DPC;
        cd  = tid - cbl * DPC;
        gb  = grp * GB + cbl;
        const int d = d0 + cd;
        const float h0 = states[(size_t)(0 * BB + gb) * DD + d];
        c_state        = states[(size_t)(1 * BB + gb) * DD + d];
        out[((size_t)(0 * BB + gb) * (TT + 1) + 0) * DD + d] = h0;
        out[((size_t)(1 * BB + gb) * (TT + 1) + 0) * DD + d] = c_state;
    }

    volatile unsigned* ctr = &g_ctr[grp * 32];

    // ── Main recurrence ──
    for (int t = 0; t < TT; ++t) {
        // Phase 1: Wx(t) + bias loads (cell threads; consumed after S3).
        float wxi = 0.f, wxf = 0.f, wxz = 0.f, wxo = 0.f;
        if (tid < GB * DPC) {
            const int d = d0 + cd;
            const float* wp = Wx + ((size_t)gb * TT + t) * (4 * DD) + d;
            wxi = wp[0 * DD] + bias[0 * DD + d];
            wxf = wp[1 * DD] + bias[1 * DD + d];
            wxz = wp[2 * DD] + bias[2 * DD + d];
            wxo = wp[3 * DD] + bias[3 * DD + d];
        }

        // Phase 2: stage packed h(t) into smem — COALESCED wide loads (the
        // R12-proven pattern), replacing narrow .cv loads in the MMA chain.
        if (t == 0) {
            for (int e = tid; e < GB * DD; e += NTHREADS) {     // 24 per thread
                const int b = e / DD, k = e - b * DD;
                sm_h[b * HPITCH + k] = pack_hilo(states[(size_t)(grp * GB + b) * DD + k]);
            }
        } else {
            const uint4* src = (const uint4*)(g_h[t & 1] + (size_t)grp * GB * DD);
            #pragma unroll
            for (int r = 0; r < 6; ++r) {                        // 1536 uint4
                const int idx = tid + r * NTHREADS;
                const int b = idx / 192, kq = idx - b * 192;     // 192 uint4/row
                uint4 v;
                ldcv_u4(v, src + idx);                           // L2-fresh
                *(uint4*)(sm_h + b * HPITCH + kq * 4) = v;
            }
        }
        __syncthreads();   // S1: staged h ready

        // Phase 3: GEMM. B fragments from smem (LDS.64 + PRMT, 29-cyc class
        // latency instead of ~250-cyc L2). 9 MMAs per K-step:
        // 3 M-tiles x (Ahi*Bhi + Ahi*Blo + Alo*Bhi). 54 HMMA / warp / step.
        float acc[NMT][4];
        #pragma unroll
        for (int m = 0; m < NMT; ++m)
            #pragma unroll
            for (int q = 0; q < 4; ++q) acc[m][q] = 0.f;
        {
            const unsigned* hr = sm_h + gid * HPITCH;            // this lane's B row
            #pragma unroll
            for (int s = 0; s < KST; ++s) {
                const int ko = kb + s * 16 + tig * 2;
                const uint2 e01 = *(const uint2*)(hr + ko);      // elems ko, ko+1
                const uint2 e89 = *(const uint2*)(hr + ko + 8);  // elems ko+8, ko+9
                const uint32_t bh0 = __byte_perm(e01.x, e01.y, 0x5410);
                const uint32_t bl0 = __byte_perm(e01.x, e01.y, 0x7632);
                const uint32_t bh1 = __byte_perm(e89.x, e89.y, 0x5410);
                const uint32_t bl1 = __byte_perm(e89.x, e89.y, 0x7632);
                #pragma unroll
                for (int m = 0; m < NMT; ++m) MMA16816(acc[m], Ahi[m][s], bh0, bh1);
                #pragma unroll
                for (int m = 0; m < NMT; ++m) MMA16816(acc[m], Ahi[m][s], bl0, bl1);
                #pragma unroll
                for (int m = 0; m < NMT; ++m) MMA16816(acc[m], Alo[m][s], bh0, bh1);
            }
        }

        // Phase 4: spill C fragments (conflict-free padded layout).
        {
            float* rw = red + (size_t)w * REDW;
            #pragma unroll
            for (int m = 0; m < NMT; ++m) {
                const int r0 = m * 16 + gid;
                const int n0 = tig * 2;
                rw[(n0    ) * NPITCH + r0    ] = acc[m][0];
                rw[(n0 + 1) * NPITCH + r0    ] = acc[m][1];
                rw[(n0    ) * NPITCH + r0 + 8] = acc[m][2];
                rw[(n0 + 1) * NPITCH + r0 + 8] = acc[m][3];
            }
        }
        __syncthreads();   // S3: all spills visible

        // Phase 5: cell threads reduce over 8 warp slices and run the update.
        float hn = 0.f, cn = 0.f;
        if (tid < GB * DPC) {
            const int off = cbl * NPITCH + cd * 4;
            float4 g4 = make_float4(0.f, 0.f, 0.f, 0.f);
            #pragma unroll
            for (int ww = 0; ww < NW; ++ww) {
                const float4 p = *(const float4*)(red + (size_t)ww * REDW + off);
                g4.x += p.x; g4.y += p.y; g4.z += p.z; g4.w += p.w;
            }
            const float gi = g4.x + wxi;
            const float gf = g4.y + wxf;
            const float gz = g4.z + wxz;
            const float go = g4.w + wxo;
            const float i_ = 1.f / (1.f + __expf(-gi));
            const float f_ = 1.f / (1.f + __expf(-gf));
            const float z_ = tanhf(gz);
            const float o_ = 1.f / (1.f + __expf(-go));
            cn = f_ * c_state + i_ * z_;
            hn = o_ * tanhf(cn);
            c_state = cn;
            // ONE packed store for the exchange (hi|lo in one u32).
            g_h[(t + 1) & 1][(size_t)gb * DD + d0 + cd] = pack_hilo(hn);
        }

        // Phase 6: PER-GROUP grid barrier — PROVEN shape (R12/R13/R15): one
        // fence + one atomicAdd per CTA (drain ~55cyc at REDG rate), per-warp
        // lane-0 volatile poll of the single counter.
        __syncthreads();                   // S_flag: all h stores issued
        if (tid == 0) {
            __threadfence();
            atomicAdd((unsigned*)ctr, 1u);
        }
        // Off-critical-path: fp32 out rows for t+1 (never read cross-CTA).
        if (tid < GB * DPC) {
            const int d = d0 + cd;
            out[((size_t)(0 * BB + gb) * (TT + 1) + (t + 1)) * DD + d] = hn;
            out[((size_t)(1 * BB + gb) * (TT + 1) + (t + 1)) * DD + d] = cn;
        }
        {
            const unsigned target = (unsigned)(GCTAS) * (unsigned)(t + 1);
            if (l == 0) {
                while (*ctr < target) { }
            }
            __syncwarp();
        }
    }
}

extern "C" void kernel_launch(void* const* d_in, const int* in_sizes, int n_in,
                              void* d_out, int out_size)
{
    const float* states = (const float*)d_in[0];  // [2,16,1,768]
    const float* Wx     = (const float*)d_in[1];  // [16,1024,4,1,768]
    const float* R      = (const float*)d_in[2];  // [4,1,768,768]
    const float* bias   = (const float*)d_in[3];  // [4,1,768]
    float*       out    = (float*)d_out;          // [2,16,1025,1,768]

    const size_t smem_bytes = (size_t)GB * HPITCH * 4 + (size_t)NW * REDW * 4; // 38144 B

    rnn_reset_kernel<<<1, 64>>>();
    rnn_mma_kernel<<<NCTA, NTHREADS, smem_bytes>>>(states, Wx, R, bias, out);
}